// round 3
// baseline (speedup 1.0000x reference)
#include <cuda_runtime.h>
#include <math.h>

#define Bq 8
#define Cc 96
#define Nn 3136
#define Mm 784
#define KD 16
#define TK 5
#define OC 192
#define C4 384
#define REFOFF (Bq*OC*Nn)

// ---------------- scratch (device globals; no allocation allowed) ----------------
__device__ float g_yt[Bq*Nn*Cc];
__device__ float g_xf[Bq*Nn*Cc];
__device__ float g_ynorm[Bq*Nn];
__device__ float g_xnorm[Bq*Nn];
__device__ float g_d[(size_t)Bq*Nn*Nn];          // 315 MB
__device__ float g_density[Bq*Nn];
__device__ unsigned g_dmax[Bq];
__device__ float g_score[Bq*Nn];
__device__ int   g_cidx[Bq*Mm];
__device__ float g_cen[Bq*Mm*Cc];
__device__ float g_cnorm[Bq*Mm];
__device__ float g_assign[(size_t)Bq*Nn*Mm];     // 79 MB (logits then probs, in place)
__device__ int   g_top5[Bq*Nn*TK];
__device__ float g_agg[Bq*Mm*Cc];
__device__ float g_hdn[Bq*Mm*C4];
__device__ float g_agg2[Bq*Mm*Cc];
__device__ float g_rel[Bq*Nn*Cc];

// ---------------- init: zero per-batch dmax (graph-replay safe) ----------------
__global__ void k_init() {
    if (threadIdx.x < Bq) g_dmax[threadIdx.x] = 0u;
}

// ---------------- transpose (B,C,N)->(B,N,C) + row norms, for y and x ----------------
__global__ void k_prep(const float* __restrict__ x, const float* __restrict__ y) {
    const float* src = blockIdx.z ? x : y;
    float* dst = blockIdx.z ? g_xf : g_yt;
    float* nrm = blockIdx.z ? g_xnorm : g_ynorm;
    int b = blockIdx.y;
    int n0 = blockIdx.x * 32;
    __shared__ float tile[Cc][33];
    int tx = threadIdx.x, ty = threadIdx.y;
    for (int c0 = ty; c0 < Cc; c0 += 8)
        tile[c0][tx] = src[((size_t)b*Cc + c0)*Nn + n0 + tx];
    __syncthreads();
    for (int nl = ty; nl < 32; nl += 8) {
        float s = 0.f;
        for (int cc = tx; cc < Cc; cc += 32) {
            float v = tile[cc][nl];
            dst[((size_t)b*Nn + n0 + nl)*Cc + cc] = v;
            s += v*v;
        }
        #pragma unroll
        for (int off = 16; off; off >>= 1) s += __shfl_xor_sync(0xffffffffu, s, off);
        if (tx == 0) nrm[b*Nn + n0 + nl] = s;
    }
}

// ---------------- d[b,i,j] = |yi|^2 + |yj|^2 - 2<yi,yj> + relpos[i,j] ----------------
__global__ void k_dist(const float* __restrict__ relpos) {
    int b = blockIdx.z;
    int i0 = blockIdx.y * 64, j0 = blockIdx.x * 64;
    __shared__ float As[16][65], Bs[16][65];
    int tx = threadIdx.x, ty = threadIdx.y;
    int t = ty*16 + tx;
    float acc[4][4] = {};
    const float* Ab = g_yt + ((size_t)b*Nn + i0)*Cc;
    const float* Bb = g_yt + ((size_t)b*Nn + j0)*Cc;
    for (int kc = 0; kc < Cc; kc += 16) {
        #pragma unroll
        for (int r = 0; r < 4; r++) {
            int e = r*256 + t; int row = e >> 4, kk = e & 15;
            As[kk][row] = Ab[row*Cc + kc + kk];
            Bs[kk][row] = Bb[row*Cc + kc + kk];
        }
        __syncthreads();
        #pragma unroll
        for (int kk = 0; kk < 16; kk++) {
            float a[4], bb[4];
            #pragma unroll
            for (int u = 0; u < 4; u++) a[u] = As[kk][ty + 16*u];
            #pragma unroll
            for (int v = 0; v < 4; v++) bb[v] = Bs[kk][tx + 16*v];
            #pragma unroll
            for (int u = 0; u < 4; u++)
                #pragma unroll
                for (int v = 0; v < 4; v++) acc[u][v] += a[u]*bb[v];
        }
        __syncthreads();
    }
    #pragma unroll
    for (int u = 0; u < 4; u++) {
        int i = i0 + ty + 16*u;
        float yi = g_ynorm[b*Nn + i];
        #pragma unroll
        for (int v = 0; v < 4; v++) {
            int j = j0 + tx + 16*v;
            float dv = yi + g_ynorm[b*Nn + j] - 2.f*acc[u][v] + relpos[(size_t)i*Nn + j];
            g_d[((size_t)(b*Nn + i))*Nn + j] = dv;
        }
    }
}

// ---------------- per-row: 16 smallest -> density; row max -> atomic dmax ----------------
__global__ void k_knn() {
    int row = blockIdx.x * 8 + (threadIdx.x >> 5);
    int lane = threadIdx.x & 31;
    int b = row / Nn;
    const float* drow = g_d + (size_t)row * Nn;
    float best[KD];
    #pragma unroll
    for (int u = 0; u < KD; u++) best[u] = 3.4e38f;
    float thr = 3.4e38f;
    float rmax = -3.4e38f;
    for (int j = lane; j < Nn; j += 32) {
        float v = drow[j];
        rmax = fmaxf(rmax, v);
        if (v < thr) {
            int p = KD - 1;
            while (p > 0 && v < best[p-1]) { best[p] = best[p-1]; --p; }
            best[p] = v;
            thr = best[KD-1];
        }
    }
    #pragma unroll
    for (int off = 16; off; off >>= 1) rmax = fmaxf(rmax, __shfl_xor_sync(0xffffffffu, rmax, off));
    // merge: extract 16 global minima across the 32 sorted per-lane lists
    int ptr = 0;
    float dsum = 0.f;
    for (int r = 0; r < KD; r++) {
        float cand = (ptr < KD) ? best[ptr] : 3.4e38f;
        float m = cand;
        #pragma unroll
        for (int off = 16; off; off >>= 1) m = fminf(m, __shfl_xor_sync(0xffffffffu, m, off));
        unsigned bal = __ballot_sync(0xffffffffu, cand == m);
        int src = __ffs(bal) - 1;
        if (lane == src) ptr++;
        dsum += m;
    }
    if (lane == 0) {
        float mean = dsum * (1.0f / 16.0f);
        // XLA-GPU semantics: expf (__nv_expf) with flush-to-zero on subnormal
        // results. Deep-underflow rows collapse to density == +0.0 exactly, so
        // their scores tie at 0 and lax.top_k falls back to index order.
        float dens = expf(-mean);
        if (dens < 1.17549435e-38f) dens = 0.0f;
        g_density[row] = dens;
        atomicMax(&g_dmax[b], __float_as_uint(rmax)); // rmax > 0 always
    }
}

// ---------------- dist_peak + score ----------------
__global__ void k_peak() {
    int row = blockIdx.x * 8 + (threadIdx.x >> 5);
    int lane = threadIdx.x & 31;
    int b = row / Nn;
    float di = g_density[row];
    float dmx = __uint_as_float(g_dmax[b]);
    const float* drow = g_d + (size_t)row * Nn;
    const float* dens = g_density + b*Nn;
    float mn = dmx;
    for (int j = lane; j < Nn; j += 32)
        if (dens[j] > di) mn = fminf(mn, drow[j]);
    #pragma unroll
    for (int off = 16; off; off >>= 1) mn = fminf(mn, __shfl_xor_sync(0xffffffffu, mn, off));
    if (lane == 0) g_score[row] = mn * di;
}

// ---------------- stable top-M by rank (matches lax.top_k tie rule: lower index first) ----------------
__global__ void k_topm() {
    int b = blockIdx.y;
    __shared__ float s[Nn];
    for (int t = threadIdx.x; t < Nn; t += 256) s[t] = g_score[b*Nn + t];
    __syncthreads();
    int i = blockIdx.x * 256 + threadIdx.x;
    if (i < Nn) {
        float si = s[i];
        int rank = 0;
        for (int j = 0; j < Nn; j++) {
            float sj = s[j];
            rank += (sj > si) || (sj == si && j < i);
        }
        if (rank < Mm) g_cidx[b*Mm + rank] = i;
    }
}

// ---------------- gather centers + norms ----------------
__global__ void k_cen() {
    int b = blockIdx.y, k = blockIdx.x;
    int idx = g_cidx[b*Mm + k];
    int c = threadIdx.x;  // 96 threads
    float v = g_yt[((size_t)b*Nn + idx)*Cc + c];
    g_cen[((size_t)b*Mm + k)*Cc + c] = v;
    float s = v*v;
    #pragma unroll
    for (int off = 16; off; off >>= 1) s += __shfl_xor_sync(0xffffffffu, s, off);
    __shared__ float ps[3];
    if ((threadIdx.x & 31) == 0) ps[threadIdx.x >> 5] = s;
    __syncthreads();
    if (threadIdx.x == 0) g_cnorm[b*Mm + k] = ps[0] + ps[1] + ps[2];
}

// ---------------- assign logits = 2<xf,cen> - |xf|^2 - |cen|^2 ----------------
__global__ void k_logits() {
    int b = blockIdx.z;
    int i0 = blockIdx.y * 64, j0 = blockIdx.x * 64;
    __shared__ float As[16][65], Bs[16][65];
    int tx = threadIdx.x, ty = threadIdx.y;
    int t = ty*16 + tx;
    float acc[4][4] = {};
    const float* Ab = g_xf + ((size_t)b*Nn + i0)*Cc;
    const float* Bb = g_cen + ((size_t)b*Mm + j0)*Cc;
    for (int kc = 0; kc < Cc; kc += 16) {
        #pragma unroll
        for (int r = 0; r < 4; r++) {
            int e = r*256 + t; int row = e >> 4, kk = e & 15;
            As[kk][row] = Ab[row*Cc + kc + kk];
            Bs[kk][row] = (j0 + row < Mm) ? Bb[row*Cc + kc + kk] : 0.f;
        }
        __syncthreads();
        #pragma unroll
        for (int kk = 0; kk < 16; kk++) {
            float a[4], bb[4];
            #pragma unroll
            for (int u = 0; u < 4; u++) a[u] = As[kk][ty + 16*u];
            #pragma unroll
            for (int v = 0; v < 4; v++) bb[v] = Bs[kk][tx + 16*v];
            #pragma unroll
            for (int u = 0; u < 4; u++)
                #pragma unroll
                for (int v = 0; v < 4; v++) acc[u][v] += a[u]*bb[v];
        }
        __syncthreads();
    }
    #pragma unroll
    for (int u = 0; u < 4; u++) {
        int i = i0 + ty + 16*u;
        float xn = g_xnorm[b*Nn + i];
        #pragma unroll
        for (int v = 0; v < 4; v++) {
            int j = j0 + tx + 16*v;
            if (j < Mm)
                g_assign[((size_t)(b*Nn + i))*Mm + j] = 2.f*acc[u][v] - xn - g_cnorm[b*Mm + j];
        }
    }
}

// ---------------- row softmax over M (in place) + stable top-5 indices ----------------
__global__ void k_softmax() {
    int row = blockIdx.x * 8 + (threadIdx.x >> 5);
    int lane = threadIdx.x & 31;
    float* arow = g_assign + (size_t)row * Mm;
    float v[25];
    float mx = -3.4e38f;
    #pragma unroll
    for (int r = 0; r < 25; r++) {
        int k = lane + r*32;
        float x = (k < Mm) ? arow[k] : -3.4e38f;
        v[r] = x;
        mx = fmaxf(mx, x);
    }
    #pragma unroll
    for (int off = 16; off; off >>= 1) mx = fmaxf(mx, __shfl_xor_sync(0xffffffffu, mx, off));
    float sum = 0.f;
    float tv[TK]; int ti[TK];
    #pragma unroll
    for (int u = 0; u < TK; u++) { tv[u] = -3.4e38f; ti[u] = 0x7fffffff; }
    #pragma unroll
    for (int r = 0; r < 25; r++) {
        int k = lane + r*32;
        float p = (k < Mm) ? expf(v[r] - mx) : 0.f;
        v[r] = p;
        sum += p;
        if (k < Mm && p > tv[TK-1]) {           // strict >: earlier (lower) k kept on ties
            tv[TK-1] = p; ti[TK-1] = k;
            #pragma unroll
            for (int u = TK-1; u > 0; u--) {
                if (tv[u] > tv[u-1]) {
                    float tf = tv[u]; tv[u] = tv[u-1]; tv[u-1] = tf;
                    int tt = ti[u]; ti[u] = ti[u-1]; ti[u-1] = tt;
                }
            }
        }
    }
    #pragma unroll
    for (int off = 16; off; off >>= 1) sum += __shfl_xor_sync(0xffffffffu, sum, off);
    #pragma unroll
    for (int r = 0; r < 25; r++) {
        int k = lane + r*32;
        if (k < Mm) arow[k] = v[r] / sum;
    }
    // warp merge top-5 with (value desc, index asc) tie rule
    int ptr = 0;
    for (int t = 0; t < TK; t++) {
        float cv = (ptr < TK) ? tv[ptr] : -3.4e38f;
        int   ci = (ptr < TK) ? ti[ptr] : 0x7fffffff;
        float wv = cv; int wi = ci;
        #pragma unroll
        for (int off = 16; off; off >>= 1) {
            float ov = __shfl_xor_sync(0xffffffffu, wv, off);
            int   oi = __shfl_xor_sync(0xffffffffu, wi, off);
            if (ov > wv || (ov == wv && oi < wi)) { wv = ov; wi = oi; }
        }
        if (ptr < TK && ci == wi) ptr++;
        if (lane == 0) g_top5[row*TK + t] = wi;
    }
}

// ---------------- agg[b,k,c] = sum_n assign[b,n,k] xf[b,n,c] / (mass+1e-6) ----------------
__global__ void k_agg() {
    int b = blockIdx.y;
    int k0 = blockIdx.x * 16;
    int tx = threadIdx.x, ty = threadIdx.y;
    int t = ty*16 + tx;
    __shared__ float As[16][17];
    __shared__ float Xs[16][97];
    float acc[6] = {};
    float mAcc = 0.f;
    for (int n0 = 0; n0 < Nn; n0 += 16) {
        As[t >> 4][t & 15] = g_assign[((size_t)(b*Nn + n0 + (t >> 4)))*Mm + k0 + (t & 15)];
        #pragma unroll
        for (int r = 0; r < 6; r++) {
            int e = r*256 + t; int nn = e / 96, cc = e % 96;
            Xs[nn][cc] = g_xf[((size_t)b*Nn + n0 + nn)*Cc + cc];
        }
        __syncthreads();
        #pragma unroll
        for (int nn = 0; nn < 16; nn++) {
            float a = As[nn][tx];
            if (ty == 0) mAcc += a;
            #pragma unroll
            for (int j = 0; j < 6; j++) acc[j] += a * Xs[nn][ty + 16*j];
        }
        __syncthreads();
    }
    __shared__ float msh[16];
    if (ty == 0) msh[tx] = mAcc;
    __syncthreads();
    float inv = 1.f / (msh[tx] + 1e-6f);
    #pragma unroll
    for (int j = 0; j < 6; j++)
        g_agg[((size_t)b*Mm + k0 + tx)*Cc + ty + 16*j] = acc[j] * inv;
}

// ---------------- FFN layer 1: hdn = relu((agg @ w1^T + b1)*g1 + bt1) ----------------
__global__ void k_ffn1(const float* __restrict__ w1, const float* __restrict__ b1,
                       const float* __restrict__ g1, const float* __restrict__ bt1) {
    int b = blockIdx.y; int k0 = blockIdx.x * 16;
    __shared__ float ag[16][97];
    int tid = threadIdx.x;
    #pragma unroll
    for (int r = 0; r < 6; r++) {
        int e = r*256 + tid; int kk = e / 96, cc = e % 96;
        ag[kk][cc] = g_agg[((size_t)b*Mm + k0 + kk)*Cc + cc];
    }
    __syncthreads();
    for (int o = tid; o < C4; o += 256) {
        float acc[16] = {};
        for (int c = 0; c < Cc; c++) {
            float w = w1[o*Cc + c];
            #pragma unroll
            for (int kk = 0; kk < 16; kk++) acc[kk] += w * ag[kk][c];
        }
        float bb = b1[o], gg = g1[o], bt = bt1[o];
        #pragma unroll
        for (int kk = 0; kk < 16; kk++) {
            float h = fmaxf((acc[kk] + bb)*gg + bt, 0.f);
            g_hdn[((size_t)b*Mm + k0 + kk)*C4 + o] = h;
        }
    }
}

// ---------------- FFN layer 2 + residual; writes agg2 and the "refined" output ----------------
__global__ void k_ffn2(const float* __restrict__ w2, const float* __restrict__ b2,
                       const float* __restrict__ g2, const float* __restrict__ bt2,
                       float* __restrict__ refined) {
    int b = blockIdx.y; int k0 = blockIdx.x * 16;
    __shared__ float hd[16][385];
    int tid = threadIdx.x;  // 192
    for (int e = tid; e < 16*C4; e += 192) {
        int kk = e / C4, oo = e % C4;
        hd[kk][oo] = g_hdn[((size_t)b*Mm + k0 + kk)*C4 + oo];
    }
    __syncthreads();
    int c = tid % 96; int kh = tid / 96;
    float acc[8] = {};
    for (int o = 0; o < C4; o++) {
        float w = w2[c*C4 + o];
        #pragma unroll
        for (int kk = 0; kk < 8; kk++) acc[kk] += w * hd[kh*8 + kk][o];
    }
    float bb = b2[c], gg = g2[c], bt = bt2[c];
    #pragma unroll
    for (int kk = 0; kk < 8; kk++) {
        int k = k0 + kh*8 + kk;
        float v = g_agg[((size_t)b*Mm + k)*Cc + c] + ((acc[kk] + bb)*gg + bt);
        g_agg2[((size_t)b*Mm + k)*Cc + c] = v;
        refined[((size_t)(b*Cc + c))*Mm + k] = v;
    }
}

// ---------------- rel[b,n,c] = max_t agg2[b, top5[t], c] - xf[b,n,c] ----------------
__global__ void k_rel() {
    int n = blockIdx.x, b = blockIdx.y;
    __shared__ int id5[TK];
    if (threadIdx.x < TK) id5[threadIdx.x] = g_top5[((size_t)b*Nn + n)*TK + threadIdx.x];
    __syncthreads();
    int c = threadIdx.x;  // 96
    float mx = -3.4e38f;
    #pragma unroll
    for (int t = 0; t < TK; t++)
        mx = fmaxf(mx, g_agg2[((size_t)b*Mm + id5[t])*Cc + c]);
    g_rel[((size_t)b*Nn + n)*Cc + c] = mx - g_xf[((size_t)b*Nn + n)*Cc + c];
}

// ---------------- final GEMM: out[b,o,n] = relu((nw@xcat + nb)*ng + nbt) ----------------
__global__ void k_out(const float* __restrict__ nw, const float* __restrict__ nb,
                      const float* __restrict__ ng, const float* __restrict__ nbt,
                      float* __restrict__ dout) {
    int b = blockIdx.y; int n0 = blockIdx.x * 32;
    __shared__ float xfs[32][97], rls[32][97];
    int tid = threadIdx.x;
    #pragma unroll
    for (int r = 0; r < 12; r++) {
        int e = r*256 + tid; int nl = e / 96, cc = e % 96;
        xfs[nl][cc] = g_xf[((size_t)b*Nn + n0 + nl)*Cc + cc];
        rls[nl][cc] = g_rel[((size_t)b*Nn + n0 + nl)*Cc + cc];
    }
    __syncthreads();
    int nl = tid & 31, ob = tid >> 5;
    for (int r = 0; r < 24; r++) {
        int o = ob*24 + r;
        const float* wrow = nw + o*2*Cc;
        float acc = 0.f;
        for (int cc = 0; cc < Cc; cc++)
            acc += wrow[2*cc] * xfs[nl][cc] + wrow[2*cc + 1] * rls[nl][cc];
        float vv = fmaxf((acc + nb[o]) * ng[o] + nbt[o], 0.f);
        dout[((size_t)(b*OC + o))*Nn + n0 + nl] = vv;
    }
}

extern "C" void kernel_launch(void* const* d_in, const int* in_sizes, int n_in,
                              void* d_out, int out_size) {
    const float* x   = (const float*)d_in[0];
    const float* rp  = (const float*)d_in[1];
    const float* y   = (const float*)d_in[2];
    const float* w1  = (const float*)d_in[3];
    const float* b1  = (const float*)d_in[4];
    const float* g1  = (const float*)d_in[5];
    const float* bt1 = (const float*)d_in[6];
    const float* w2  = (const float*)d_in[7];
    const float* b2  = (const float*)d_in[8];
    const float* g2  = (const float*)d_in[9];
    const float* bt2 = (const float*)d_in[10];
    const float* nw  = (const float*)d_in[11];
    const float* nb  = (const float*)d_in[12];
    const float* ng  = (const float*)d_in[13];
    const float* nbt = (const float*)d_in[14];
    float* out = (float*)d_out;

    k_init<<<1, 32>>>();
    k_prep<<<dim3(Nn/32, Bq, 2), dim3(32, 8)>>>(x, y);
    k_dist<<<dim3(Nn/64, Nn/64, Bq), dim3(16, 16)>>>(rp);
    k_knn<<<Bq*Nn/8, 256>>>();
    k_peak<<<Bq*Nn/8, 256>>>();
    k_topm<<<dim3((Nn + 255)/256, Bq), 256>>>();
    k_cen<<<dim3(Mm, Bq), 96>>>();
    k_logits<<<dim3((Mm + 63)/64, Nn/64, Bq), dim3(16, 16)>>>();
    k_softmax<<<Bq*Nn/8, 256>>>();
    k_agg<<<dim3(Mm/16, Bq), dim3(16, 16)>>>();
    k_ffn1<<<dim3(Mm/16, Bq), 256>>>(w1, b1, g1, bt1);
    k_ffn2<<<dim3(Mm/16, Bq), 192>>>(w2, b2, g2, bt2, out + REFOFF);
    k_rel<<<dim3(Nn, Bq), 96>>>();
    k_out<<<dim3(Nn/32, Bq), 256>>>(nw, nb, ng, nbt, out);
}